// round 2
// baseline (speedup 1.0000x reference)
#include <cuda_runtime.h>

// LinearInverse_45664092291621
//
// Reference returns y + score(y) = y - y = 0 exactly (score(x) = -x), so the
// output is zeros((1048576, 2), float32) = 8 MB of zeros. Optimal kernel is a
// pure zero-fill. R1 showed the fill lands in L2 (DRAM=0%), so the ceiling is
// the LTS cap (~6300 B/cyc => ~1 us); R1's 4.8 us was CTA-dispatch-bound
// (2048 tiny blocks). This version: 512 blocks x 256 threads x 4 float4
// stores, fully unrolled, no predication on the fast path.

#define THREADS 256
#define F4_PER_THREAD 4
#define F4_PER_BLOCK (THREADS * F4_PER_THREAD)   // 1024 float4 = 16 KB per block

__global__ void __launch_bounds__(THREADS) zero_fill_fat(float4* __restrict__ out) {
    float4* p = out + (size_t)blockIdx.x * F4_PER_BLOCK + threadIdx.x;
    const float4 z = make_float4(0.0f, 0.0f, 0.0f, 0.0f);
#pragma unroll
    for (int k = 0; k < F4_PER_THREAD; ++k) {
        p[k * THREADS] = z;
    }
}

// Generic fallback for sizes that don't divide evenly (not hit for this problem).
__global__ void __launch_bounds__(THREADS) zero_fill_guarded(float* __restrict__ out,
                                                             int start, int n) {
    int i = start + blockIdx.x * blockDim.x + threadIdx.x;
    if (i < n) out[i] = 0.0f;
}

extern "C" void kernel_launch(void* const* d_in, const int* in_sizes, int n_in,
                              void* d_out, int out_size) {
    (void)d_in; (void)in_sizes; (void)n_in;

    float* out = (float*)d_out;

    int elems_per_block = F4_PER_BLOCK * 4;           // 4096 floats per block
    int full_blocks = out_size / elems_per_block;

    if (full_blocks > 0) {
        zero_fill_fat<<<full_blocks, THREADS>>>((float4*)out);
    }

    int covered = full_blocks * elems_per_block;
    if (covered < out_size) {
        int rem = out_size - covered;
        int blocks = (rem + THREADS - 1) / THREADS;
        zero_fill_guarded<<<blocks, THREADS>>>(out, covered, out_size);
    }
}

// round 4
// speedup vs baseline: 1.0829x; 1.0829x over previous
#include <cuda_runtime.h>

// LinearInverse_45664092291621
//
// Reference returns y + score(y) = y - y = 0 exactly (score(x) = -x):
// output is zeros((1048576, 2), float32) = 8 MB of zeros.
//
// R1/R2 evidence: a hand-written STG.128 zero-fill is shape-invariant at
// ~4.7 us (L2=16%, ~1.74 TB/s, issue=3.5%) -- the SM store/writeback path is
// the wall, not dispatch or issue. So switch paths entirely: a graph memset
// node (cudaMemsetAsync during capture) uses the driver's tuned fill, and
// collapses the graph to a single node.
//
// R3 was an infra failure (container never ran) -- resubmitting unchanged.
//
// cudaMemsetAsync is graph-capturable (memset node), allocation-free, and
// deterministic. Zeros are bytewise zero, so one byte-memset of the whole
// float32 buffer is exact for any out_size.

extern "C" void kernel_launch(void* const* d_in, const int* in_sizes, int n_in,
                              void* d_out, int out_size) {
    (void)d_in; (void)in_sizes; (void)n_in;
    // out_size elements of float32 -> 4 bytes each.
    cudaMemsetAsync(d_out, 0, (size_t)out_size * sizeof(float), 0);
}